// round 1
// baseline (speedup 1.0000x reference)
#include <cuda_runtime.h>
#include <math.h>
#include <stdint.h>

// Problem constants (shapes fixed by setup_inputs)
#define Hh 384
#define Ww 384
#define HW (Hh*Ww)          // 147456
#define MAXB 4
#define CC 64               // channels
#define PP 2048             // max positives
#define KCc 20480           // rim candidate pool
#define KNn 10240           // max negatives
#define RCOLS (PP+KNn)      // 12288 loss columns
#define RAD 5               // dilation radius (kernel 11)
#define NBLK (HW/1024)      // 144 compaction blocks per image
#define NSPLIT 6
#define INV_T 10.0f
#define TILE_SMEM (2*64*129*4)   // 66048 bytes dynamic smem for GEMM tiles

// ------------------------- scratch (device globals) -------------------------
__device__ unsigned char g_fg [MAXB][HW];
__device__ unsigned char g_hd [MAXB][HW];
__device__ unsigned char g_rim[MAXB][HW];
__device__ int   g_bcnt[MAXB][NBLK][2];
__device__ int   g_boff[MAXB][NBLK][2];
__device__ int   g_tot [MAXB][2];          // [0]=total fg, [1]=total rim
__device__ int   g_pidx[MAXB][PP];
__device__ int   g_cidx[MAXB][KCc];
__device__ float g_pf  [MAXB][PP][CC];     // normalized positive features
__device__ float g_cf  [MAXB][KCc][CC];    // normalized candidate features
__device__ float g_maxsim[MAXB][KCc];
__device__ int   g_nsel[MAXB][KNn];
__device__ int   g_ksel[MAXB];
__device__ float g_partLpp[MAXB][NSPLIT][PP];
__device__ float g_partExp[MAXB][NSPLIT][PP];
__device__ float g_imgloss[MAXB];
__device__ int   g_has[MAXB];

// ------------------------- masks: fg + dilation ------------------------------
__global__ void k_fg(const long long* __restrict__ labels, int tot){
    int i = blockIdx.x*256 + threadIdx.x;
    if (i < tot) ((unsigned char*)g_fg)[i] = (labels[i] > 0) ? 1 : 0;
}
__global__ void k_hdil(int tot){
    int i = blockIdx.x*256 + threadIdx.x;
    if (i >= tot) return;
    int b = i / HW, p = i % HW;
    int row = p / Ww, col = p % Ww;
    const unsigned char* fr = &g_fg[b][row*Ww];
    int lo = col-RAD; if (lo < 0) lo = 0;
    int hi = col+RAD; if (hi > Ww-1) hi = Ww-1;
    unsigned char m = 0;
    for (int c = lo; c <= hi; c++) m |= fr[c];
    ((unsigned char*)g_hd)[i] = m;
}
__global__ void k_vdil(int tot){
    int i = blockIdx.x*256 + threadIdx.x;
    if (i >= tot) return;
    int b = i / HW, p = i % HW;
    int row = p / Ww, col = p % Ww;
    int lo = row-RAD; if (lo < 0) lo = 0;
    int hi = row+RAD; if (hi > Hh-1) hi = Hh-1;
    unsigned char m = 0;
    for (int r = lo; r <= hi; r++) m |= g_hd[b][r*Ww + col];
    ((unsigned char*)g_rim)[i] = (m && !g_fg[b][p]) ? 1 : 0;
}

// ------------------------- ordered compaction -------------------------------
__global__ void k_count(){
    int b = blockIdx.y, blk = blockIdx.x, tid = threadIdx.x;
    int base = blk*1024 + tid*4;
    int cf = 0, cr = 0;
    #pragma unroll
    for (int e = 0; e < 4; e++){ cf += g_fg[b][base+e]; cr += g_rim[b][base+e]; }
    __shared__ int sf, sr;
    if (tid == 0){ sf = 0; sr = 0; }
    __syncthreads();
    atomicAdd(&sf, cf); atomicAdd(&sr, cr);
    __syncthreads();
    if (tid == 0){ g_bcnt[b][blk][0] = sf; g_bcnt[b][blk][1] = sr; }
}
__global__ void k_scan(){
    int b = blockIdx.x;
    if (threadIdx.x == 0){
        int a0 = 0, a1 = 0;
        for (int k = 0; k < NBLK; k++){
            g_boff[b][k][0] = a0; a0 += g_bcnt[b][k][0];
            g_boff[b][k][1] = a1; a1 += g_bcnt[b][k][1];
        }
        g_tot[b][0] = a0; g_tot[b][1] = a1;
    }
}
__global__ void k_scatter(){
    int b = blockIdx.y, blk = blockIdx.x, tid = threadIdx.x;
    int base = blk*1024 + tid*4;
    unsigned char ff[4], rr[4];
    int lf = 0, lr = 0;
    #pragma unroll
    for (int e = 0; e < 4; e++){
        ff[e] = g_fg[b][base+e];  rr[e] = g_rim[b][base+e];
        lf += ff[e]; lr += rr[e];
    }
    __shared__ int sc[256];
    int own = lf | (lr << 16);
    sc[tid] = own;
    __syncthreads();
    for (int off = 1; off < 256; off <<= 1){
        int v = (tid >= off) ? sc[tid-off] : 0;
        __syncthreads();
        sc[tid] += v;
        __syncthreads();
    }
    int ex = sc[tid] - own;
    int offF = g_boff[b][blk][0] + (ex & 0xffff);
    int offR = g_boff[b][blk][1] + (ex >> 16);
    #pragma unroll
    for (int e = 0; e < 4; e++){
        if (ff[e]){ if (offF < PP)  g_pidx[b][offF] = base+e; offF++; }
        if (rr[e]){ if (offR < KCc) g_cidx[b][offR] = base+e; offR++; }
    }
}

// ------------------------- gather + L2 normalize ----------------------------
__global__ void k_gather(const float* __restrict__ feat, int B){
    int wid = (blockIdx.x*blockDim.x + threadIdx.x) >> 5;
    int lane = threadIdx.x & 31;
    int per = PP + KCc;
    if (wid >= B*per) return;
    int b = wid / per, s = wid % per;
    float* dst; int slot, cnt; const int* idxArr;
    if (s < PP){ slot = s;      cnt = min(g_tot[b][0], PP);  dst = g_pf[b][s];      idxArr = g_pidx[b]; }
    else       { slot = s - PP; cnt = min(g_tot[b][1], KCc); dst = g_cf[b][s - PP]; idxArr = g_cidx[b]; }
    float v0 = 0.f, v1 = 0.f;
    if (slot < cnt){
        int pix = idxArr[slot];
        const float* fp = feat + (size_t)b*CC*HW + pix;
        v0 = fp[(size_t)lane*HW];
        v1 = fp[(size_t)(lane+32)*HW];
        float ss = v0*v0 + v1*v1;
        #pragma unroll
        for (int off = 16; off > 0; off >>= 1) ss += __shfl_xor_sync(0xffffffffu, ss, off);
        float inv = 1.f / fmaxf(sqrtf(ss), 1e-8f);
        v0 *= inv; v1 *= inv;
    }
    dst[lane] = v0; dst[lane+32] = v1;
}

// ------------------------- mining GEMM + column max -------------------------
__global__ void __launch_bounds__(256, 2) k_sim(){
    int b = blockIdx.y, ct = blockIdx.x, tid = threadIdx.x;
    int tr = tid >> 4, tc = tid & 15;
    extern __shared__ float sh[];
    float* sB = sh;               // [64][129] candidate tile (k-major)
    float* sA = sh + 64*129;      // [64][129] positive chunk (k-major)
    __shared__ float red[16][129];
    int nposE  = min(g_tot[b][0], PP);
    int ncandE = min(g_tot[b][1], KCc);
    for (int l = tid; l < 128*64; l += 256){
        int cc = l >> 6, k = l & 63;
        int slot = ct*128 + cc;
        sB[k*129 + cc] = (slot < ncandE) ? g_cf[b][slot][k] : 0.f;
    }
    float cmax[8];
    #pragma unroll
    for (int j = 0; j < 8; j++) cmax[j] = -INFINITY;
    for (int chunk = 0; chunk < PP/128; chunk++){
        __syncthreads();
        for (int l = tid; l < 128*64; l += 256){
            int rr = l >> 6, k = l & 63;
            int slot = chunk*128 + rr;
            sA[k*129 + rr] = (slot < nposE) ? g_pf[b][slot][k] : 0.f;
        }
        __syncthreads();
        float acc[8][8];
        #pragma unroll
        for (int i = 0; i < 8; i++)
            #pragma unroll
            for (int j = 0; j < 8; j++) acc[i][j] = 0.f;
        #pragma unroll 8
        for (int k = 0; k < 64; k++){
            float a[8], bb[8];
            #pragma unroll
            for (int i = 0; i < 8; i++) a[i]  = sA[k*129 + tr*8 + i];
            #pragma unroll
            for (int j = 0; j < 8; j++) bb[j] = sB[k*129 + tc*8 + j];
            #pragma unroll
            for (int i = 0; i < 8; i++)
                #pragma unroll
                for (int j = 0; j < 8; j++) acc[i][j] = fmaf(a[i], bb[j], acc[i][j]);
        }
        int rbase = chunk*128 + tr*8;
        #pragma unroll
        for (int i = 0; i < 8; i++){
            if (rbase + i < nposE){
                #pragma unroll
                for (int j = 0; j < 8; j++) cmax[j] = fmaxf(cmax[j], acc[i][j]);
            }
        }
    }
    #pragma unroll
    for (int j = 0; j < 8; j++) red[tr][tc*8 + j] = cmax[j];
    __syncthreads();
    if (tid < 128){
        float m = -INFINITY;
        #pragma unroll
        for (int r = 0; r < 16; r++) m = fmaxf(m, red[r][tid]);
        int slot = ct*128 + tid;
        g_maxsim[b][slot] = (slot < ncandE && nposE > 0) ? m : -INFINITY;
    }
}

// ------------------------- radix top-K select -------------------------------
__device__ __forceinline__ unsigned int simkey(int b, int c, int ncandE){
    float v = (c < ncandE) ? g_maxsim[b][c] : -INFINITY;
    unsigned int u = __float_as_uint(v);
    return (u & 0x80000000u) ? ~u : (u | 0x80000000u);
}
__global__ void k_select(){
    int b = blockIdx.x, tid = threadIdx.x;
    __shared__ int hist[256];
    __shared__ int sChosen, sRem;
    __shared__ int scg[256], sce[256];
    int nposE  = min(g_tot[b][0], PP);
    int ncandE = min(g_tot[b][1], KCc);
    int nallow = min(5*nposE, KNn);
    int Ksel = min(nallow, ncandE);
    if (nposE == 0) Ksel = 0;
    if (tid == 0) g_ksel[b] = Ksel;
    if (Ksel == 0) return;

    unsigned int prefix = 0, prefMask = 0;
    int remK = Ksel;
    for (int byte = 3; byte >= 0; byte--){
        hist[tid] = 0;
        __syncthreads();
        int shift = byte*8;
        for (int c = tid; c < KCc; c += 256){
            unsigned int k = simkey(b, c, ncandE);
            if ((k & prefMask) == prefix) atomicAdd(&hist[(k >> shift) & 255], 1);
        }
        __syncthreads();
        if (tid == 0){
            int cum = 0, chosen = 0;
            for (int d = 255; d >= 0; d--){
                if (cum + hist[d] >= remK){ chosen = d; break; }
                cum += hist[d];
            }
            sChosen = chosen; sRem = remK - cum;
        }
        __syncthreads();
        prefix  |= ((unsigned int)sChosen) << shift;
        prefMask |= 0xFFu << shift;
        remK = sRem;
        __syncthreads();
    }
    unsigned int T = prefix;   // threshold key; remK entries == T are taken
    // ordered compaction over contiguous per-thread ranges (80 each)
    int begin = tid*80, end = begin + 80;
    int cg = 0, ce = 0;
    for (int c = begin; c < end; c++){
        unsigned int k = simkey(b, c, ncandE);
        if (k > T) cg++; else if (k == T) ce++;
    }
    scg[tid] = cg; sce[tid] = ce;
    __syncthreads();
    for (int off = 1; off < 256; off <<= 1){
        int a1 = (tid >= off) ? scg[tid-off] : 0;
        int a2 = (tid >= off) ? sce[tid-off] : 0;
        __syncthreads();
        scg[tid] += a1; sce[tid] += a2;
        __syncthreads();
    }
    int gOff = scg[tid] - cg;
    int eOff = sce[tid] - ce;
    int count_gt = scg[255];
    for (int c = begin; c < end; c++){
        unsigned int k = simkey(b, c, ncandE);
        if (k > T){ g_nsel[b][gOff++] = c; }
        else if (k == T){
            if (eOff < remK) g_nsel[b][count_gt + eOff] = c;
            eOff++;
        }
    }
}

// ------------------------- fused loss GEMM ----------------------------------
__global__ void __launch_bounds__(256, 2) k_loss(){
    int b = blockIdx.z, rt = blockIdx.x, sp = blockIdx.y;
    int tid = threadIdx.x;
    int tr = tid >> 4, tc = tid & 15;
    extern __shared__ float sh[];
    float* sB = sh;               // [64][129] column tile
    float* sA = sh + 64*129;      // [64][129] row tile (fixed per block)
    __shared__ float red[16][129];
    int nposE = min(g_tot[b][0], PP);
    int Ksel = g_ksel[b];
    for (int l = tid; l < 128*64; l += 256){
        int rr = l >> 6, k = l & 63;
        int slot = rt*128 + rr;
        sA[k*129 + rr] = (slot < nposE) ? g_pf[b][slot][k] : 0.f;
    }
    float slpp[8], sexp[8];
    #pragma unroll
    for (int i = 0; i < 8; i++){ slpp[i] = 0.f; sexp[i] = 0.f; }

    for (int t = 0; t < 16; t++){
        int colBase = sp*2048 + t*128;
        __syncthreads();
        for (int l = tid; l < 128*64; l += 256){
            int cc = l >> 6, k = l & 63;
            int jg = colBase + cc;
            float v = 0.f;
            if (jg < PP){ if (jg < nposE) v = g_pf[b][jg][k]; }
            else { int kn = jg - PP; if (kn < Ksel) v = g_cf[b][g_nsel[b][kn]][k]; }
            sB[k*129 + cc] = v;
        }
        __syncthreads();
        float acc[8][8];
        #pragma unroll
        for (int i = 0; i < 8; i++)
            #pragma unroll
            for (int j = 0; j < 8; j++) acc[i][j] = 0.f;
        #pragma unroll 8
        for (int k = 0; k < 64; k++){
            float a[8], bb[8];
            #pragma unroll
            for (int i = 0; i < 8; i++) a[i]  = sA[k*129 + tr*8 + i];
            #pragma unroll
            for (int j = 0; j < 8; j++) bb[j] = sB[k*129 + tc*8 + j];
            #pragma unroll
            for (int i = 0; i < 8; i++)
                #pragma unroll
                for (int j = 0; j < 8; j++) acc[i][j] = fmaf(a[i], bb[j], acc[i][j]);
        }
        int ig0 = rt*128 + tr*8;
        #pragma unroll
        for (int j = 0; j < 8; j++){
            int jg = colBase + tc*8 + j;
            bool validPP = (jg < PP) && (jg < nposE);
            bool validPN = (jg >= PP) && (jg - PP < Ksel);
            #pragma unroll
            for (int i = 0; i < 8; i++){
                float lp = acc[i][j] * INV_T;
                if (validPP){
                    if (jg != ig0 + i){ slpp[i] += lp; sexp[i] += __expf(lp); }
                } else if (validPN){
                    sexp[i] += __expf(lp);
                }
            }
        }
    }
    #pragma unroll
    for (int i = 0; i < 8; i++) red[tc][tr*8 + i] = slpp[i];
    __syncthreads();
    if (tid < 128){
        float s = 0.f;
        #pragma unroll
        for (int r = 0; r < 16; r++) s += red[r][tid];
        g_partLpp[b][sp][rt*128 + tid] = s;
    }
    __syncthreads();
    #pragma unroll
    for (int i = 0; i < 8; i++) red[tc][tr*8 + i] = sexp[i];
    __syncthreads();
    if (tid < 128){
        float s = 0.f;
        #pragma unroll
        for (int r = 0; r < 16; r++) s += red[r][tid];
        g_partExp[b][sp][rt*128 + tid] = s;
    }
}

// ------------------------- per-image loss + final ---------------------------
__global__ void k_final(){
    int b = blockIdx.x, tid = threadIdx.x;
    int nposE = min(g_tot[b][0], PP);
    int npairs = nposE - 1;
    float sum = 0.f; int cnt = 0;
    if (npairs > 0){
        for (int r = tid; r < nposE; r += 256){
            float sl = 0.f, se = 0.f;
            #pragma unroll
            for (int sp = 0; sp < NSPLIT; sp++){ sl += g_partLpp[b][sp][r]; se += g_partExp[b][sp][r]; }
            sum += logf(se) - sl/(float)npairs;
            cnt++;
        }
    }
    __shared__ float ssum[256];
    __shared__ int scnt[256];
    ssum[tid] = sum; scnt[tid] = cnt;
    __syncthreads();
    for (int s = 128; s > 0; s >>= 1){
        if (tid < s){ ssum[tid] += ssum[tid+s]; scnt[tid] += scnt[tid+s]; }
        __syncthreads();
    }
    if (tid == 0){
        g_imgloss[b] = (scnt[0] > 0) ? ssum[0]/(float)scnt[0] : 0.f;
        g_has[b] = (scnt[0] > 0) ? 1 : 0;
    }
}
__global__ void k_out(float* out, int B){
    float s = 0.f; int c = 0;
    for (int b = 0; b < B; b++) if (g_has[b]){ s += g_imgloss[b]; c++; }
    out[0] = s / (float)(c > 0 ? c : 1);
}

// ------------------------- launch -------------------------------------------
extern "C" void kernel_launch(void* const* d_in, const int* in_sizes, int n_in,
                              void* d_out, int out_size){
    const float* feat = (const float*)d_in[0];
    const long long* labels = (const long long*)d_in[1];
    int B = in_sizes[1] / HW;
    if (B < 1) B = 1; if (B > MAXB) B = MAXB;

    cudaFuncSetAttribute(k_sim,  cudaFuncAttributeMaxDynamicSharedMemorySize, TILE_SMEM);
    cudaFuncSetAttribute(k_loss, cudaFuncAttributeMaxDynamicSharedMemorySize, TILE_SMEM);

    int tot = B*HW;
    int nb = (tot + 255)/256;
    k_fg  <<<nb, 256>>>(labels, tot);
    k_hdil<<<nb, 256>>>(tot);
    k_vdil<<<nb, 256>>>(tot);
    dim3 gc(NBLK, B);
    k_count  <<<gc, 256>>>();
    k_scan   <<<B, 32>>>();
    k_scatter<<<gc, 256>>>();
    int warps = B*(PP + KCc);
    k_gather<<<(warps*32 + 255)/256, 256>>>(feat, B);
    k_sim   <<<dim3(KCc/128, B), 256, TILE_SMEM>>>();
    k_select<<<B, 256>>>();
    k_loss  <<<dim3(PP/128, NSPLIT, B), 256, TILE_SMEM>>>();
    k_final <<<B, 256>>>();
    k_out   <<<1, 1>>>((float*)d_out, B);
}

// round 3
// speedup vs baseline: 2.2575x; 2.2575x over previous
#include <cuda_runtime.h>
#include <cuda_bf16.h>
#include <math.h>
#include <stdint.h>

// Problem constants (shapes fixed by setup_inputs)
#define Hh 384
#define Ww 384
#define HW (Hh*Ww)          // 147456
#define MAXB 4
#define CC 64               // channels
#define PP 2048             // max positives
#define KCc 20480           // rim candidate pool
#define KNn 10240           // max negatives
#define RAD 5               // dilation radius (kernel 11)
#define NBLK (HW/1024)      // 144 compaction blocks per image
#define NSPLIT 6
#define INV_T 10.0f

// ---- mma tile config ----
#define LDA 72              // padded row stride in bf16 (144 B): conflict-free frags
#define ROWB 144            // bytes per padded row
#define TILE_B (128*ROWB)   // 18432 bytes per tile buffer
#define SM_AHI 0
#define SM_ALO (TILE_B)
#define SM_BHI (2*TILE_B)
#define SM_BLO (3*TILE_B)
#define SM_TOTAL (4*TILE_B) // 73728 bytes dynamic smem

// ------------------------- scratch (device globals) -------------------------
__device__ unsigned char g_fg [MAXB][HW];
__device__ unsigned char g_hd [MAXB][HW];
__device__ unsigned char g_rim[MAXB][HW];
__device__ int   g_bcnt[MAXB][NBLK][2];
__device__ int   g_boff[MAXB][NBLK][2];
__device__ int   g_tot [MAXB][2];          // [0]=total fg, [1]=total rim
__device__ int   g_pidx[MAXB][PP];
__device__ int   g_cidx[MAXB][KCc];
__device__ __nv_bfloat16 g_pf_hi[MAXB][PP][CC];
__device__ __nv_bfloat16 g_pf_lo[MAXB][PP][CC];
__device__ __nv_bfloat16 g_cf_hi[MAXB][KCc][CC];
__device__ __nv_bfloat16 g_cf_lo[MAXB][KCc][CC];
__device__ float g_maxsim[MAXB][KCc];
__device__ int   g_nsel[MAXB][KNn];
__device__ int   g_ksel[MAXB];
__device__ float g_partLpp[MAXB][NSPLIT][PP];
__device__ float g_partExp[MAXB][NSPLIT][PP];
__device__ float g_imgloss[MAXB];
__device__ int   g_has[MAXB];

// ------------------------- mma helper ---------------------------------------
__device__ __forceinline__ void mma_bf16(float* d, const uint32_t* a, const uint32_t* b){
    asm volatile(
        "mma.sync.aligned.m16n8k16.row.col.f32.bf16.bf16.f32 "
        "{%0,%1,%2,%3}, {%4,%5,%6,%7}, {%8,%9}, {%0,%1,%2,%3};"
        : "+f"(d[0]), "+f"(d[1]), "+f"(d[2]), "+f"(d[3])
        : "r"(a[0]), "r"(a[1]), "r"(a[2]), "r"(a[3]), "r"(b[0]), "r"(b[1]));
}

// ------------------------- masks: fg + dilation ------------------------------
__global__ void k_fg(const long long* __restrict__ labels, int tot){
    int i = blockIdx.x*256 + threadIdx.x;
    if (i < tot) ((unsigned char*)g_fg)[i] = (labels[i] > 0) ? 1 : 0;
}
__global__ void k_hdil(int tot){
    int i = blockIdx.x*256 + threadIdx.x;
    if (i >= tot) return;
    int b = i / HW, p = i % HW;
    int row = p / Ww, col = p % Ww;
    const unsigned char* fr = &g_fg[b][row*Ww];
    int lo = col-RAD; if (lo < 0) lo = 0;
    int hi = col+RAD; if (hi > Ww-1) hi = Ww-1;
    unsigned char m = 0;
    for (int c = lo; c <= hi; c++) m |= fr[c];
    ((unsigned char*)g_hd)[i] = m;
}
__global__ void k_vdil(int tot){
    int i = blockIdx.x*256 + threadIdx.x;
    if (i >= tot) return;
    int b = i / HW, p = i % HW;
    int row = p / Ww, col = p % Ww;
    int lo = row-RAD; if (lo < 0) lo = 0;
    int hi = row+RAD; if (hi > Hh-1) hi = Hh-1;
    unsigned char m = 0;
    for (int r = lo; r <= hi; r++) m |= g_hd[b][r*Ww + col];
    ((unsigned char*)g_rim)[i] = (m && !g_fg[b][p]) ? 1 : 0;
}

// ------------------------- ordered compaction -------------------------------
__global__ void k_count(){
    int b = blockIdx.y, blk = blockIdx.x, tid = threadIdx.x;
    int base = blk*1024 + tid*4;
    int cf = 0, cr = 0;
    #pragma unroll
    for (int e = 0; e < 4; e++){ cf += g_fg[b][base+e]; cr += g_rim[b][base+e]; }
    __shared__ int sf, sr;
    if (tid == 0){ sf = 0; sr = 0; }
    __syncthreads();
    atomicAdd(&sf, cf); atomicAdd(&sr, cr);
    __syncthreads();
    if (tid == 0){ g_bcnt[b][blk][0] = sf; g_bcnt[b][blk][1] = sr; }
}
__global__ void k_scan(){
    int b = blockIdx.x;
    if (threadIdx.x == 0){
        int a0 = 0, a1 = 0;
        for (int k = 0; k < NBLK; k++){
            g_boff[b][k][0] = a0; a0 += g_bcnt[b][k][0];
            g_boff[b][k][1] = a1; a1 += g_bcnt[b][k][1];
        }
        g_tot[b][0] = a0; g_tot[b][1] = a1;
    }
}
__global__ void k_scatter(){
    int b = blockIdx.y, blk = blockIdx.x, tid = threadIdx.x;
    int base = blk*1024 + tid*4;
    unsigned char ff[4], rr[4];
    int lf = 0, lr = 0;
    #pragma unroll
    for (int e = 0; e < 4; e++){
        ff[e] = g_fg[b][base+e];  rr[e] = g_rim[b][base+e];
        lf += ff[e]; lr += rr[e];
    }
    __shared__ int sc[256];
    int own = lf | (lr << 16);
    sc[tid] = own;
    __syncthreads();
    for (int off = 1; off < 256; off <<= 1){
        int v = (tid >= off) ? sc[tid-off] : 0;
        __syncthreads();
        sc[tid] += v;
        __syncthreads();
    }
    int ex = sc[tid] - own;
    int offF = g_boff[b][blk][0] + (ex & 0xffff);
    int offR = g_boff[b][blk][1] + (ex >> 16);
    #pragma unroll
    for (int e = 0; e < 4; e++){
        if (ff[e]){ if (offF < PP)  g_pidx[b][offF] = base+e; offF++; }
        if (rr[e]){ if (offR < KCc) g_cidx[b][offR] = base+e; offR++; }
    }
}

// ------------------------- gather + L2 normalize -> bf16 hi/lo ---------------
__global__ void k_gather(const float* __restrict__ feat, int B){
    int wid = (blockIdx.x*blockDim.x + threadIdx.x) >> 5;
    int lane = threadIdx.x & 31;
    int per = PP + KCc;
    if (wid >= B*per) return;
    int b = wid / per, s = wid % per;
    __nv_bfloat16 *dstH, *dstL;
    int slot, cnt; const int* idxArr;
    if (s < PP){ slot = s;      cnt = min(g_tot[b][0], PP);  dstH = g_pf_hi[b][s];      dstL = g_pf_lo[b][s];      idxArr = g_pidx[b]; }
    else       { slot = s - PP; cnt = min(g_tot[b][1], KCc); dstH = g_cf_hi[b][s - PP]; dstL = g_cf_lo[b][s - PP]; idxArr = g_cidx[b]; }
    float v0 = 0.f, v1 = 0.f;
    if (slot < cnt){
        int pix = idxArr[slot];
        const float* fp = feat + (size_t)b*CC*HW + pix;
        v0 = fp[(size_t)lane*HW];
        v1 = fp[(size_t)(lane+32)*HW];
        float ss = v0*v0 + v1*v1;
        #pragma unroll
        for (int off = 16; off > 0; off >>= 1) ss += __shfl_xor_sync(0xffffffffu, ss, off);
        float inv = 1.f / fmaxf(sqrtf(ss), 1e-8f);
        v0 *= inv; v1 *= inv;
    }
    __nv_bfloat16 h0 = __float2bfloat16(v0);
    __nv_bfloat16 h1 = __float2bfloat16(v1);
    dstH[lane]    = h0;  dstL[lane]    = __float2bfloat16(v0 - __bfloat162float(h0));
    dstH[lane+32] = h1;  dstL[lane+32] = __float2bfloat16(v1 - __bfloat162float(h1));
}

// ------------------------- shared tile loader (padded, 16B stores) ----------
// src rows are 64 bf16 = 128 B contiguous; dst rows padded to 144 B.
__device__ __forceinline__ void stage_tile(char* dst, const __nv_bfloat16* src){
    // copy one 128-byte row chunk: caller iterates
    *(uint4*)dst = *(const uint4*)src;
}

// ------------------------- mining: mma GEMM + row-max -----------------------
// Block: 128 candidates (A/M) x loop over positives in 128-col chunks.
// 8 warps = 4 (m) x 2 (n); warp tile 32 x 64.
__global__ void __launch_bounds__(256) k_simM(){
    int b = blockIdx.y, ct = blockIdx.x;
    int tid = threadIdx.x, wid = tid >> 5, lane = tid & 31;
    int warpm = wid & 3, warpn = wid >> 2;
    int g = lane >> 2, tig = lane & 3;
    extern __shared__ char sm[];
    __shared__ float redM[128][2];
    int nposE  = min(g_tot[b][0], PP);
    int ncandE = min(g_tot[b][1], KCc);

    // stage A (128 candidates, hi+lo) once
    for (int i = tid; i < 128*8; i += 256){
        int row = i >> 3, q = i & 7;
        int slot = ct*128 + row;
        uint4 vh = make_uint4(0,0,0,0), vl = make_uint4(0,0,0,0);
        if (slot < ncandE){
            vh = ((const uint4*)g_cf_hi[b][slot])[q];
            vl = ((const uint4*)g_cf_lo[b][slot])[q];
        }
        *(uint4*)(sm + SM_AHI + row*ROWB + q*16) = vh;
        *(uint4*)(sm + SM_ALO + row*ROWB + q*16) = vl;
    }

    float acc[2][8][4];
    #pragma unroll
    for (int mt = 0; mt < 2; mt++)
        #pragma unroll
        for (int nt = 0; nt < 8; nt++)
            #pragma unroll
            for (int r = 0; r < 4; r++) acc[mt][nt][r] = 0.f;
    float rowmax[4] = {-INFINITY, -INFINITY, -INFINITY, -INFINITY};

    int m0 = warpm*32, n0 = warpn*64;
    for (int chunk = 0; chunk < PP/128; chunk++){
        __syncthreads();
        for (int i = tid; i < 128*8; i += 256){
            int row = i >> 3, q = i & 7;
            int slot = chunk*128 + row;
            uint4 vh = make_uint4(0,0,0,0), vl = make_uint4(0,0,0,0);
            if (slot < nposE){
                vh = ((const uint4*)g_pf_hi[b][slot])[q];
                vl = ((const uint4*)g_pf_lo[b][slot])[q];
            }
            *(uint4*)(sm + SM_BHI + row*ROWB + q*16) = vh;
            *(uint4*)(sm + SM_BLO + row*ROWB + q*16) = vl;
        }
        __syncthreads();
        #pragma unroll
        for (int ks = 0; ks < 4; ks++){
            int kb = ks*32 + tig*4;           // byte offset of k pair
            uint32_t Ah[2][4], Al[2][4];
            #pragma unroll
            for (int mt = 0; mt < 2; mt++){
                int abase = (m0 + mt*16 + g)*ROWB + kb;
                Ah[mt][0] = *(uint32_t*)(sm + SM_AHI + abase);
                Ah[mt][1] = *(uint32_t*)(sm + SM_AHI + abase + 8*ROWB);
                Ah[mt][2] = *(uint32_t*)(sm + SM_AHI + abase + 16);
                Ah[mt][3] = *(uint32_t*)(sm + SM_AHI + abase + 8*ROWB + 16);
                Al[mt][0] = *(uint32_t*)(sm + SM_ALO + abase);
                Al[mt][1] = *(uint32_t*)(sm + SM_ALO + abase + 8*ROWB);
                Al[mt][2] = *(uint32_t*)(sm + SM_ALO + abase + 16);
                Al[mt][3] = *(uint32_t*)(sm + SM_ALO + abase + 8*ROWB + 16);
            }
            #pragma unroll
            for (int nt = 0; nt < 8; nt++){
                int bbase = (n0 + nt*8 + g)*ROWB + kb;
                uint32_t Bh[2], Bl[2];
                Bh[0] = *(uint32_t*)(sm + SM_BHI + bbase);
                Bh[1] = *(uint32_t*)(sm + SM_BHI + bbase + 16);
                Bl[0] = *(uint32_t*)(sm + SM_BLO + bbase);
                Bl[1] = *(uint32_t*)(sm + SM_BLO + bbase + 16);
                #pragma unroll
                for (int mt = 0; mt < 2; mt++){
                    mma_bf16(acc[mt][nt], Ah[mt], Bh);
                    mma_bf16(acc[mt][nt], Ah[mt], Bl);
                    mma_bf16(acc[mt][nt], Al[mt], Bh);
                }
            }
        }
        // epilogue: column-validity masked max, reset acc
        int colChunk = chunk*128;
        #pragma unroll
        for (int mt = 0; mt < 2; mt++){
            #pragma unroll
            for (int nt = 0; nt < 8; nt++){
                int cbase = colChunk + n0 + nt*8 + tig*2;
                #pragma unroll
                for (int r = 0; r < 4; r++){
                    int col = cbase + (r & 1);
                    if (col < nposE){
                        int slot = mt*2 + (r >> 1);
                        rowmax[slot] = fmaxf(rowmax[slot], acc[mt][nt][r]);
                    }
                    acc[mt][nt][r] = 0.f;
                }
            }
        }
    }
    // reduce across tig lanes (same row)
    #pragma unroll
    for (int s = 0; s < 4; s++){
        rowmax[s] = fmaxf(rowmax[s], __shfl_xor_sync(0xffffffffu, rowmax[s], 1));
        rowmax[s] = fmaxf(rowmax[s], __shfl_xor_sync(0xffffffffu, rowmax[s], 2));
    }
    if (tig == 0){
        #pragma unroll
        for (int s = 0; s < 4; s++){
            int lrow = m0 + (s >> 1)*16 + g + (s & 1)*8;
            redM[lrow][warpn] = rowmax[s];
        }
    }
    __syncthreads();
    if (tid < 128){
        float m = fmaxf(redM[tid][0], redM[tid][1]);
        int slot = ct*128 + tid;
        if (slot < KCc)
            g_maxsim[b][slot] = (slot < ncandE && nposE > 0) ? m : -INFINITY;
    }
}

// ------------------------- radix top-K select -------------------------------
__device__ __forceinline__ unsigned int simkey(int b, int c, int ncandE){
    float v = (c < ncandE) ? g_maxsim[b][c] : -INFINITY;
    unsigned int u = __float_as_uint(v);
    return (u & 0x80000000u) ? ~u : (u | 0x80000000u);
}
__global__ void k_select(){
    int b = blockIdx.x, tid = threadIdx.x;
    __shared__ int hist[256];
    __shared__ int sChosen, sRem;
    __shared__ int scg[256], sce[256];
    int nposE  = min(g_tot[b][0], PP);
    int ncandE = min(g_tot[b][1], KCc);
    int nallow = min(5*nposE, KNn);
    int Ksel = min(nallow, ncandE);
    if (nposE == 0) Ksel = 0;
    if (tid == 0) g_ksel[b] = Ksel;
    if (Ksel == 0) return;

    unsigned int prefix = 0, prefMask = 0;
    int remK = Ksel;
    for (int byte = 3; byte >= 0; byte--){
        hist[tid] = 0;
        __syncthreads();
        int shift = byte*8;
        for (int c = tid; c < KCc; c += 256){
            unsigned int k = simkey(b, c, ncandE);
            if ((k & prefMask) == prefix) atomicAdd(&hist[(k >> shift) & 255], 1);
        }
        __syncthreads();
        if (tid == 0){
            int cum = 0, chosen = 0;
            for (int d = 255; d >= 0; d--){
                if (cum + hist[d] >= remK){ chosen = d; break; }
                cum += hist[d];
            }
            sChosen = chosen; sRem = remK - cum;
        }
        __syncthreads();
        prefix  |= ((unsigned int)sChosen) << shift;
        prefMask |= 0xFFu << shift;
        remK = sRem;
        __syncthreads();
    }
    unsigned int T = prefix;
    int begin = tid*80, end = begin + 80;
    int cg = 0, ce = 0;
    for (int c = begin; c < end; c++){
        unsigned int k = simkey(b, c, ncandE);
        if (k > T) cg++; else if (k == T) ce++;
    }
    scg[tid] = cg; sce[tid] = ce;
    __syncthreads();
    for (int off = 1; off < 256; off <<= 1){
        int a1 = (tid >= off) ? scg[tid-off] : 0;
        int a2 = (tid >= off) ? sce[tid-off] : 0;
        __syncthreads();
        scg[tid] += a1; sce[tid] += a2;
        __syncthreads();
    }
    int gOff = scg[tid] - cg;
    int eOff = sce[tid] - ce;
    int count_gt = scg[255];
    for (int c = begin; c < end; c++){
        unsigned int k = simkey(b, c, ncandE);
        if (k > T){ g_nsel[b][gOff++] = c; }
        else if (k == T){
            if (eOff < remK) g_nsel[b][count_gt + eOff] = c;
            eOff++;
        }
    }
}

// ------------------------- loss: mma GEMM + fused epilogue ------------------
// Block: 128 positives (A/M rows, fixed) x 16 chunks of 128 cols in split sp.
__global__ void __launch_bounds__(256) k_lossM(){
    int b = blockIdx.z, rt = blockIdx.x, sp = blockIdx.y;
    int tid = threadIdx.x, wid = tid >> 5, lane = tid & 31;
    int warpm = wid & 3, warpn = wid >> 2;
    int g = lane >> 2, tig = lane & 3;
    extern __shared__ char sm[];
    __shared__ float redL[128][2];
    __shared__ float redE[128][2];
    int nposE = min(g_tot[b][0], PP);
    int Ksel  = g_ksel[b];

    for (int i = tid; i < 128*8; i += 256){
        int row = i >> 3, q = i & 7;
        int slot = rt*128 + row;
        uint4 vh = make_uint4(0,0,0,0), vl = make_uint4(0,0,0,0);
        if (slot < nposE){
            vh = ((const uint4*)g_pf_hi[b][slot])[q];
            vl = ((const uint4*)g_pf_lo[b][slot])[q];
        }
        *(uint4*)(sm + SM_AHI + row*ROWB + q*16) = vh;
        *(uint4*)(sm + SM_ALO + row*ROWB + q*16) = vl;
    }

    float acc[2][8][4];
    #pragma unroll
    for (int mt = 0; mt < 2; mt++)
        #pragma unroll
        for (int nt = 0; nt < 8; nt++)
            #pragma unroll
            for (int r = 0; r < 4; r++) acc[mt][nt][r] = 0.f;
    float slpp[4] = {0.f,0.f,0.f,0.f};
    float sexp[4] = {0.f,0.f,0.f,0.f};

    int m0 = warpm*32, n0 = warpn*64;
    for (int chunk = 0; chunk < 16; chunk++){
        int colBase = sp*2048 + chunk*128;
        __syncthreads();
        for (int i = tid; i < 128*8; i += 256){
            int row = i >> 3, q = i & 7;
            int jg = colBase + row;
            const __nv_bfloat16 *srcH = 0, *srcL = 0;
            if (jg < PP){
                if (jg < nposE){ srcH = g_pf_hi[b][jg]; srcL = g_pf_lo[b][jg]; }
            } else {
                int kn = jg - PP;
                if (kn < Ksel){ int cs = g_nsel[b][kn]; srcH = g_cf_hi[b][cs]; srcL = g_cf_lo[b][cs]; }
            }
            uint4 vh = srcH ? ((const uint4*)srcH)[q] : make_uint4(0,0,0,0);
            uint4 vl = srcL ? ((const uint4*)srcL)[q] : make_uint4(0,0,0,0);
            *(uint4*)(sm + SM_BHI + row*ROWB + q*16) = vh;
            *(uint4*)(sm + SM_BLO + row*ROWB + q*16) = vl;
        }
        __syncthreads();
        #pragma unroll
        for (int ks = 0; ks < 4; ks++){
            int kb = ks*32 + tig*4;
            uint32_t Ah[2][4], Al[2][4];
            #pragma unroll
            for (int mt = 0; mt < 2; mt++){
                int abase = (m0 + mt*16 + g)*ROWB + kb;
                Ah[mt][0] = *(uint32_t*)(sm + SM_AHI + abase);
                Ah[mt][1] = *(uint32_t*)(sm + SM_AHI + abase + 8*ROWB);
                Ah[mt][2] = *(uint32_t*)(sm + SM_AHI + abase + 16);
                Ah[mt][3] = *(uint32_t*)(sm + SM_AHI + abase + 8*ROWB + 16);
                Al[mt][0] = *(uint32_t*)(sm + SM_ALO + abase);
                Al[mt][1] = *(uint32_t*)(sm + SM_ALO + abase + 8*ROWB);
                Al[mt][2] = *(uint32_t*)(sm + SM_ALO + abase + 16);
                Al[mt][3] = *(uint32_t*)(sm + SM_ALO + abase + 8*ROWB + 16);
            }
            #pragma unroll
            for (int nt = 0; nt < 8; nt++){
                int bbase = (n0 + nt*8 + g)*ROWB + kb;
                uint32_t Bh[2], Bl[2];
                Bh[0] = *(uint32_t*)(sm + SM_BHI + bbase);
                Bh[1] = *(uint32_t*)(sm + SM_BHI + bbase + 16);
                Bl[0] = *(uint32_t*)(sm + SM_BLO + bbase);
                Bl[1] = *(uint32_t*)(sm + SM_BLO + bbase + 16);
                #pragma unroll
                for (int mt = 0; mt < 2; mt++){
                    mma_bf16(acc[mt][nt], Ah[mt], Bh);
                    mma_bf16(acc[mt][nt], Ah[mt], Bl);
                    mma_bf16(acc[mt][nt], Al[mt], Bh);
                }
            }
        }
        // fused epilogue: mask + logit + exp, reset acc
        #pragma unroll
        for (int mt = 0; mt < 2; mt++){
            #pragma unroll
            for (int nt = 0; nt < 8; nt++){
                int cbase = colBase + n0 + nt*8 + tig*2;
                #pragma unroll
                for (int r = 0; r < 4; r++){
                    int jg = cbase + (r & 1);
                    int slot = mt*2 + (r >> 1);
                    int myrow = rt*128 + m0 + mt*16 + g + (r >> 1)*8;
                    float lp = acc[mt][nt][r] * INV_T;
                    if (jg < PP){
                        if (jg < nposE && jg != myrow){
                            slpp[slot] += lp;
                            sexp[slot] += __expf(lp);
                        }
                    } else if (jg - PP < Ksel){
                        sexp[slot] += __expf(lp);
                    }
                    acc[mt][nt][r] = 0.f;
                }
            }
        }
    }
    // reduce across tig lanes (disjoint cols, same row)
    #pragma unroll
    for (int s = 0; s < 4; s++){
        slpp[s] += __shfl_xor_sync(0xffffffffu, slpp[s], 1);
        slpp[s] += __shfl_xor_sync(0xffffffffu, slpp[s], 2);
        sexp[s] += __shfl_xor_sync(0xffffffffu, sexp[s], 1);
        sexp[s] += __shfl_xor_sync(0xffffffffu, sexp[s], 2);
    }
    if (tig == 0){
        #pragma unroll
        for (int s = 0; s < 4; s++){
            int lrow = m0 + (s >> 1)*16 + g + (s & 1)*8;
            redL[lrow][warpn] = slpp[s];
            redE[lrow][warpn] = sexp[s];
        }
    }
    __syncthreads();
    if (tid < 128){
        g_partLpp[b][sp][rt*128 + tid] = redL[tid][0] + redL[tid][1];
        g_partExp[b][sp][rt*128 + tid] = redE[tid][0] + redE[tid][1];
    }
}

// ------------------------- per-image loss + final ---------------------------
__global__ void k_final(){
    int b = blockIdx.x, tid = threadIdx.x;
    int nposE = min(g_tot[b][0], PP);
    int npairs = nposE - 1;
    float sum = 0.f; int cnt = 0;
    if (npairs > 0){
        for (int r = tid; r < nposE; r += 256){
            float sl = 0.f, se = 0.f;
            #pragma unroll
            for (int sp = 0; sp < NSPLIT; sp++){ sl += g_partLpp[b][sp][r]; se += g_partExp[b][sp][r]; }
            sum += logf(se) - sl/(float)npairs;
            cnt++;
        }
    }
    __shared__ float ssum[256];
    __shared__ int scnt[256];
    ssum[tid] = sum; scnt[tid] = cnt;
    __syncthreads();
    for (int s = 128; s > 0; s >>= 1){
        if (tid < s){ ssum[tid] += ssum[tid+s]; scnt[tid] += scnt[tid+s]; }
        __syncthreads();
    }
    if (tid == 0){
        g_imgloss[b] = (scnt[0] > 0) ? ssum[0]/(float)scnt[0] : 0.f;
        g_has[b] = (scnt[0] > 0) ? 1 : 0;
    }
}
__global__ void k_out(float* out, int B){
    float s = 0.f; int c = 0;
    for (int b = 0; b < B; b++) if (g_has[b]){ s += g_imgloss[b]; c++; }
    out[0] = s / (float)(c > 0 ? c : 1);
}

// ------------------------- launch -------------------------------------------
extern "C" void kernel_launch(void* const* d_in, const int* in_sizes, int n_in,
                              void* d_out, int out_size){
    const float* feat = (const float*)d_in[0];
    const long long* labels = (const long long*)d_in[1];
    int B = in_sizes[1] / HW;
    if (B < 1) B = 1; if (B > MAXB) B = MAXB;

    cudaFuncSetAttribute(k_simM,  cudaFuncAttributeMaxDynamicSharedMemorySize, SM_TOTAL);
    cudaFuncSetAttribute(k_lossM, cudaFuncAttributeMaxDynamicSharedMemorySize, SM_TOTAL);

    int tot = B*HW;
    int nb = (tot + 255)/256;
    k_fg  <<<nb, 256>>>(labels, tot);
    k_hdil<<<nb, 256>>>(tot);
    k_vdil<<<nb, 256>>>(tot);
    dim3 gc(NBLK, B);
    k_count  <<<gc, 256>>>();
    k_scan   <<<B, 32>>>();
    k_scatter<<<gc, 256>>>();
    int warps = B*(PP + KCc);
    k_gather<<<(warps*32 + 255)/256, 256>>>(feat, B);
    k_simM  <<<dim3(KCc/128, B), 256, SM_TOTAL>>>();
    k_select<<<B, 256>>>();
    k_lossM <<<dim3(PP/128, NSPLIT, B), 256, SM_TOTAL>>>();
    k_final <<<B, 256>>>();
    k_out   <<<1, 1>>>((float*)d_out, B);
}

// round 4
// speedup vs baseline: 3.0352x; 1.3445x over previous
#include <cuda_runtime.h>
#include <cuda_fp16.h>
#include <math.h>
#include <stdint.h>

// Problem constants (shapes fixed by setup_inputs)
#define Hh 384
#define Ww 384
#define HW (Hh*Ww)          // 147456
#define MAXB 4
#define CC 64               // channels
#define PP 2048             // max positives
#define KCc 20480           // rim candidate pool
#define KNn 10240           // max negatives
#define RAD 5               // dilation radius (kernel 11)
#define NBLK (HW/1024)      // 144 compaction blocks per image
#define NSPLIT 6
#define INV_T 10.0f

// ---- mma tile config ----
#define ROWB 144            // bytes per padded row (72 fp16): conflict-free frags
#define TILE_B (128*ROWB)   // 18432 bytes per tile buffer
// sim kernel: A hi + B hi
#define SIM_SMEM (2*TILE_B)            // 36864
// loss kernel: A hi/lo + B hi/lo
#define LS_AHI 0
#define LS_ALO (TILE_B)
#define LS_BHI (2*TILE_B)
#define LS_BLO (3*TILE_B)
#define LS_SMEM (4*TILE_B)             // 73728

// ------------------------- scratch (device globals) -------------------------
__device__ unsigned char g_fg [MAXB][HW];
__device__ unsigned char g_hd [MAXB][HW];
__device__ unsigned char g_rim[MAXB][HW];
__device__ int   g_bcnt[MAXB][NBLK][2];
__device__ int   g_boff[MAXB][NBLK][2];
__device__ int   g_tot [MAXB][2];          // [0]=total fg, [1]=total rim
__device__ int   g_pidx[MAXB][PP];
__device__ int   g_cidx[MAXB][KCc];
__device__ __half g_pf_hi[MAXB][PP][CC];
__device__ __half g_pf_lo[MAXB][PP][CC];
__device__ __half g_cf_hi[MAXB][KCc][CC];
__device__ float g_maxsim[MAXB][KCc];
__device__ int   g_nsel[MAXB][KNn];
__device__ int   g_ksel[MAXB];
__device__ float g_partLpp[MAXB][NSPLIT][PP];
__device__ float g_partExp[MAXB][NSPLIT][PP];
__device__ float g_imgloss[MAXB];
__device__ int   g_has[MAXB];

// ------------------------- mma helper ---------------------------------------
__device__ __forceinline__ void mma_fp16(float* d, const uint32_t* a, const uint32_t* b){
    asm volatile(
        "mma.sync.aligned.m16n8k16.row.col.f32.f16.f16.f32 "
        "{%0,%1,%2,%3}, {%4,%5,%6,%7}, {%8,%9}, {%0,%1,%2,%3};"
        : "+f"(d[0]), "+f"(d[1]), "+f"(d[2]), "+f"(d[3])
        : "r"(a[0]), "r"(a[1]), "r"(a[2]), "r"(a[3]), "r"(b[0]), "r"(b[1]));
}

// ------------------------- masks: fg + dilation ------------------------------
__global__ void k_fg(const long long* __restrict__ labels, int tot){
    int i = blockIdx.x*256 + threadIdx.x;
    if (i < tot) ((unsigned char*)g_fg)[i] = (labels[i] > 0) ? 1 : 0;
}
__global__ void k_hdil(int tot){
    int i = blockIdx.x*256 + threadIdx.x;
    if (i >= tot) return;
    int b = i / HW, p = i % HW;
    int row = p / Ww, col = p % Ww;
    const unsigned char* fr = &g_fg[b][row*Ww];
    int lo = col-RAD; if (lo < 0) lo = 0;
    int hi = col+RAD; if (hi > Ww-1) hi = Ww-1;
    unsigned char m = 0;
    for (int c = lo; c <= hi; c++) m |= fr[c];
    ((unsigned char*)g_hd)[i] = m;
}
__global__ void k_vdil(int tot){
    int i = blockIdx.x*256 + threadIdx.x;
    if (i >= tot) return;
    int b = i / HW, p = i % HW;
    int row = p / Ww, col = p % Ww;
    int lo = row-RAD; if (lo < 0) lo = 0;
    int hi = row+RAD; if (hi > Hh-1) hi = Hh-1;
    unsigned char m = 0;
    for (int r = lo; r <= hi; r++) m |= g_hd[b][r*Ww + col];
    ((unsigned char*)g_rim)[i] = (m && !g_fg[b][p]) ? 1 : 0;
}

// ------------------------- ordered compaction -------------------------------
__global__ void k_count(){
    int b = blockIdx.y, blk = blockIdx.x, tid = threadIdx.x;
    int base = blk*1024 + tid*4;
    int cf = 0, cr = 0;
    #pragma unroll
    for (int e = 0; e < 4; e++){ cf += g_fg[b][base+e]; cr += g_rim[b][base+e]; }
    __shared__ int sf, sr;
    if (tid == 0){ sf = 0; sr = 0; }
    __syncthreads();
    atomicAdd(&sf, cf); atomicAdd(&sr, cr);
    __syncthreads();
    if (tid == 0){ g_bcnt[b][blk][0] = sf; g_bcnt[b][blk][1] = sr; }
}
__global__ void k_scan(){
    int b = blockIdx.x;
    if (threadIdx.x == 0){
        int a0 = 0, a1 = 0;
        for (int k = 0; k < NBLK; k++){
            g_boff[b][k][0] = a0; a0 += g_bcnt[b][k][0];
            g_boff[b][k][1] = a1; a1 += g_bcnt[b][k][1];
        }
        g_tot[b][0] = a0; g_tot[b][1] = a1;
    }
}
__global__ void k_scatter(){
    int b = blockIdx.y, blk = blockIdx.x, tid = threadIdx.x;
    int base = blk*1024 + tid*4;
    unsigned char ff[4], rr[4];
    int lf = 0, lr = 0;
    #pragma unroll
    for (int e = 0; e < 4; e++){
        ff[e] = g_fg[b][base+e];  rr[e] = g_rim[b][base+e];
        lf += ff[e]; lr += rr[e];
    }
    __shared__ int sc[256];
    int own = lf | (lr << 16);
    sc[tid] = own;
    __syncthreads();
    for (int off = 1; off < 256; off <<= 1){
        int v = (tid >= off) ? sc[tid-off] : 0;
        __syncthreads();
        sc[tid] += v;
        __syncthreads();
    }
    int ex = sc[tid] - own;
    int offF = g_boff[b][blk][0] + (ex & 0xffff);
    int offR = g_boff[b][blk][1] + (ex >> 16);
    #pragma unroll
    for (int e = 0; e < 4; e++){
        if (ff[e]){ if (offF < PP)  g_pidx[b][offF] = base+e; offF++; }
        if (rr[e]){ if (offR < KCc) g_cidx[b][offR] = base+e; offR++; }
    }
}

// ------------------------- gather + L2 normalize -> fp16 hi/lo ---------------
__global__ void k_gather(const float* __restrict__ feat, int B){
    int wid = (blockIdx.x*blockDim.x + threadIdx.x) >> 5;
    int lane = threadIdx.x & 31;
    int per = PP + KCc;
    if (wid >= B*per) return;
    int b = wid / per, s = wid % per;
    float v0 = 0.f, v1 = 0.f;
    bool isP = (s < PP);
    int slot = isP ? s : s - PP;
    int cnt  = isP ? min(g_tot[b][0], PP) : min(g_tot[b][1], KCc);
    const int* idxArr = isP ? g_pidx[b] : g_cidx[b];
    if (slot < cnt){
        int pix = idxArr[slot];
        const float* fp = feat + (size_t)b*CC*HW + pix;
        v0 = fp[(size_t)lane*HW];
        v1 = fp[(size_t)(lane+32)*HW];
        float ss = v0*v0 + v1*v1;
        #pragma unroll
        for (int off = 16; off > 0; off >>= 1) ss += __shfl_xor_sync(0xffffffffu, ss, off);
        float inv = 1.f / fmaxf(sqrtf(ss), 1e-8f);
        v0 *= inv; v1 *= inv;
    }
    __half h0 = __float2half_rn(v0);
    __half h1 = __float2half_rn(v1);
    if (isP){
        g_pf_hi[b][slot][lane]    = h0;
        g_pf_hi[b][slot][lane+32] = h1;
        g_pf_lo[b][slot][lane]    = __float2half_rn(v0 - __half2float(h0));
        g_pf_lo[b][slot][lane+32] = __float2half_rn(v1 - __half2float(h1));
    } else {
        g_cf_hi[b][slot][lane]    = h0;
        g_cf_hi[b][slot][lane+32] = h1;
    }
}

// ------------------------- mining: 1-pass fp16 mma + row-max ----------------
// Block: 128 candidates (A) x loop over positives (B) in 128-col chunks.
// 8 warps = 4 (m) x 2 (n); warp tile 32 x 64.
__global__ void __launch_bounds__(256) k_simM(){
    int b = blockIdx.y, ct = blockIdx.x;
    int tid = threadIdx.x, wid = tid >> 5, lane = tid & 31;
    int warpm = wid & 3, warpn = wid >> 2;
    int g = lane >> 2, tig = lane & 3;
    extern __shared__ char sm[];
    char* sA = sm;
    char* sB = sm + TILE_B;
    __shared__ float redM[128][2];
    int nposE  = min(g_tot[b][0], PP);
    int ncandE = min(g_tot[b][1], KCc);

    // stage A (128 candidates, hi) once
    for (int i = tid; i < 128*8; i += 256){
        int row = i >> 3, q = i & 7;
        int slot = ct*128 + row;
        uint4 v = make_uint4(0,0,0,0);
        if (slot < ncandE) v = ((const uint4*)g_cf_hi[b][slot])[q];
        *(uint4*)(sA + row*ROWB + q*16) = v;
    }

    float acc[2][8][4];
    #pragma unroll
    for (int mt = 0; mt < 2; mt++)
        #pragma unroll
        for (int nt = 0; nt < 8; nt++)
            #pragma unroll
            for (int r = 0; r < 4; r++) acc[mt][nt][r] = 0.f;
    float rowmax[4] = {-INFINITY, -INFINITY, -INFINITY, -INFINITY};

    int m0 = warpm*32, n0 = warpn*64;
    for (int chunk = 0; chunk < PP/128; chunk++){
        __syncthreads();
        for (int i = tid; i < 128*8; i += 256){
            int row = i >> 3, q = i & 7;
            int slot = chunk*128 + row;
            uint4 v = make_uint4(0,0,0,0);
            if (slot < nposE) v = ((const uint4*)g_pf_hi[b][slot])[q];
            *(uint4*)(sB + row*ROWB + q*16) = v;
        }
        __syncthreads();
        #pragma unroll
        for (int ks = 0; ks < 4; ks++){
            int kb = ks*32 + tig*4;
            uint32_t Ah[2][4];
            #pragma unroll
            for (int mt = 0; mt < 2; mt++){
                int abase = (m0 + mt*16 + g)*ROWB + kb;
                Ah[mt][0] = *(uint32_t*)(sA + abase);
                Ah[mt][1] = *(uint32_t*)(sA + abase + 8*ROWB);
                Ah[mt][2] = *(uint32_t*)(sA + abase + 16);
                Ah[mt][3] = *(uint32_t*)(sA + abase + 8*ROWB + 16);
            }
            #pragma unroll
            for (int nt = 0; nt < 8; nt++){
                int bbase = (n0 + nt*8 + g)*ROWB + kb;
                uint32_t Bh[2];
                Bh[0] = *(uint32_t*)(sB + bbase);
                Bh[1] = *(uint32_t*)(sB + bbase + 16);
                #pragma unroll
                for (int mt = 0; mt < 2; mt++)
                    mma_fp16(acc[mt][nt], Ah[mt], Bh);
            }
        }
        // epilogue: column-validity masked max, reset acc
        int colChunk = chunk*128;
        #pragma unroll
        for (int mt = 0; mt < 2; mt++){
            #pragma unroll
            for (int nt = 0; nt < 8; nt++){
                int cbase = colChunk + n0 + nt*8 + tig*2;
                #pragma unroll
                for (int r = 0; r < 4; r++){
                    int col = cbase + (r & 1);
                    if (col < nposE){
                        int slot = mt*2 + (r >> 1);
                        rowmax[slot] = fmaxf(rowmax[slot], acc[mt][nt][r]);
                    }
                    acc[mt][nt][r] = 0.f;
                }
            }
        }
    }
    #pragma unroll
    for (int s = 0; s < 4; s++){
        rowmax[s] = fmaxf(rowmax[s], __shfl_xor_sync(0xffffffffu, rowmax[s], 1));
        rowmax[s] = fmaxf(rowmax[s], __shfl_xor_sync(0xffffffffu, rowmax[s], 2));
    }
    if (tig == 0){
        #pragma unroll
        for (int s = 0; s < 4; s++){
            int lrow = m0 + (s >> 1)*16 + g + (s & 1)*8;
            redM[lrow][warpn] = rowmax[s];
        }
    }
    __syncthreads();
    if (tid < 128){
        float m = fmaxf(redM[tid][0], redM[tid][1]);
        int slot = ct*128 + tid;
        if (slot < KCc)
            g_maxsim[b][slot] = (slot < ncandE && nposE > 0) ? m : -INFINITY;
    }
}

// ------------------------- radix top-K select -------------------------------
__device__ __forceinline__ unsigned int simkey(int b, int c, int ncandE){
    float v = (c < ncandE) ? g_maxsim[b][c] : -INFINITY;
    unsigned int u = __float_as_uint(v);
    return (u & 0x80000000u) ? ~u : (u | 0x80000000u);
}
__global__ void k_select(){
    int b = blockIdx.x, tid = threadIdx.x;
    __shared__ int hist[256];
    __shared__ int sChosen, sRem;
    __shared__ int scg[256], sce[256];
    int nposE  = min(g_tot[b][0], PP);
    int ncandE = min(g_tot[b][1], KCc);
    int nallow = min(5*nposE, KNn);
    int Ksel = min(nallow, ncandE);
    if (nposE == 0) Ksel = 0;
    if (tid == 0) g_ksel[b] = Ksel;
    if (Ksel == 0) return;

    unsigned int prefix = 0, prefMask = 0;
    int remK = Ksel;
    for (int byte = 3; byte >= 0; byte--){
        hist[tid] = 0;
        __syncthreads();
        int shift = byte*8;
        for (int c = tid; c < KCc; c += 256){
            unsigned int k = simkey(b, c, ncandE);
            if ((k & prefMask) == prefix) atomicAdd(&hist[(k >> shift) & 255], 1);
        }
        __syncthreads();
        if (tid == 0){
            int cum = 0, chosen = 0;
            for (int d = 255; d >= 0; d--){
                if (cum + hist[d] >= remK){ chosen = d; break; }
                cum += hist[d];
            }
            sChosen = chosen; sRem = remK - cum;
        }
        __syncthreads();
        prefix  |= ((unsigned int)sChosen) << shift;
        prefMask |= 0xFFu << shift;
        remK = sRem;
        __syncthreads();
    }
    unsigned int T = prefix;
    int begin = tid*80, end = begin + 80;
    int cg = 0, ce = 0;
    for (int c = begin; c < end; c++){
        unsigned int k = simkey(b, c, ncandE);
        if (k > T) cg++; else if (k == T) ce++;
    }
    scg[tid] = cg; sce[tid] = ce;
    __syncthreads();
    for (int off = 1; off < 256; off <<= 1){
        int a1 = (tid >= off) ? scg[tid-off] : 0;
        int a2 = (tid >= off) ? sce[tid-off] : 0;
        __syncthreads();
        scg[tid] += a1; sce[tid] += a2;
        __syncthreads();
    }
    int gOff = scg[tid] - cg;
    int eOff = sce[tid] - ce;
    int count_gt = scg[255];
    for (int c = begin; c < end; c++){
        unsigned int k = simkey(b, c, ncandE);
        if (k > T){ g_nsel[b][gOff++] = c; }
        else if (k == T){
            if (eOff < remK) g_nsel[b][count_gt + eOff] = c;
            eOff++;
        }
    }
}

// ------------------------- loss: mma GEMM + fused epilogue ------------------
// TP=1: pp block (split 0), 3-pass hi/lo compensated.
// TP=0: pn blocks (splits 1..5), 1-pass hi only.
template<int TP>
__global__ void __launch_bounds__(256) k_lossM(int spBase){
    int b = blockIdx.z, rt = blockIdx.x, sp = spBase + blockIdx.y;
    int tid = threadIdx.x, wid = tid >> 5, lane = tid & 31;
    int warpm = wid & 3, warpn = wid >> 2;
    int g = lane >> 2, tig = lane & 3;
    extern __shared__ char sm[];
    __shared__ float redL[128][2];
    __shared__ float redE[128][2];
    int nposE = min(g_tot[b][0], PP);
    int Ksel  = g_ksel[b];

    // stage A (pf hi, + lo if TP)
    for (int i = tid; i < 128*8; i += 256){
        int row = i >> 3, q = i & 7;
        int slot = rt*128 + row;
        uint4 vh = make_uint4(0,0,0,0);
        if (slot < nposE) vh = ((const uint4*)g_pf_hi[b][slot])[q];
        *(uint4*)(sm + LS_AHI + row*ROWB + q*16) = vh;
        if (TP){
            uint4 vl = make_uint4(0,0,0,0);
            if (slot < nposE) vl = ((const uint4*)g_pf_lo[b][slot])[q];
            *(uint4*)(sm + LS_ALO + row*ROWB + q*16) = vl;
        }
    }

    float acc[2][8][4];
    #pragma unroll
    for (int mt = 0; mt < 2; mt++)
        #pragma unroll
        for (int nt = 0; nt < 8; nt++)
            #pragma unroll
            for (int r = 0; r < 4; r++) acc[mt][nt][r] = 0.f;
    float slpp[4] = {0.f,0.f,0.f,0.f};
    float sexp[4] = {0.f,0.f,0.f,0.f};

    int m0 = warpm*32, n0 = warpn*64;
    for (int chunk = 0; chunk < 16; chunk++){
        int colBase = sp*2048 + chunk*128;
        __syncthreads();
        for (int i = tid; i < 128*8; i += 256){
            int row = i >> 3, q = i & 7;
            int jg = colBase + row;
            if (TP){
                uint4 vh = make_uint4(0,0,0,0), vl = make_uint4(0,0,0,0);
                if (jg < nposE){
                    vh = ((const uint4*)g_pf_hi[b][jg])[q];
                    vl = ((const uint4*)g_pf_lo[b][jg])[q];
                }
                *(uint4*)(sm + LS_BHI + row*ROWB + q*16) = vh;
                *(uint4*)(sm + LS_BLO + row*ROWB + q*16) = vl;
            } else {
                int kn = jg - PP;
                uint4 vh = make_uint4(0,0,0,0);
                if (kn < Ksel) vh = ((const uint4*)g_cf_hi[b][g_nsel[b][kn]])[q];
                *(uint4*)(sm + LS_BHI + row*ROWB + q*16) = vh;
            }
        }
        __syncthreads();
        #pragma unroll
        for (int ks = 0; ks < 4; ks++){
            int kb = ks*32 + tig*4;
            uint32_t Ah[2][4], Al[2][4];
            #pragma unroll
            for (int mt = 0; mt < 2; mt++){
                int abase = (m0 + mt*16 + g)*ROWB + kb;
                Ah[mt][0] = *(uint32_t*)(sm + LS_AHI + abase);
                Ah[mt][1] = *(uint32_t*)(sm + LS_AHI + abase + 8*ROWB);
                Ah[mt][2] = *(uint32_t*)(sm + LS_AHI + abase + 16);
                Ah[mt][3] = *(uint32_t*)(sm + LS_AHI + abase + 8*ROWB + 16);
                if (TP){
                    Al[mt][0] = *(uint32_t*)(sm + LS_ALO + abase);
                    Al[mt][1] = *(uint32_t*)(sm + LS_ALO + abase + 8*ROWB);
                    Al[mt][2] = *(uint32_t*)(sm + LS_ALO + abase + 16);
                    Al[mt][3] = *(uint32_t*)(sm + LS_ALO + abase + 8*ROWB + 16);
                }
            }
            #pragma unroll
            for (int nt = 0; nt < 8; nt++){
                int bbase = (n0 + nt*8 + g)*ROWB + kb;
                uint32_t Bh[2], Bl[2];
                Bh[0] = *(uint32_t*)(sm + LS_BHI + bbase);
                Bh[1] = *(uint32_t*)(sm + LS_BHI + bbase + 16);
                if (TP){
                    Bl[0] = *(uint32_t*)(sm + LS_BLO + bbase);
                    Bl[1] = *(uint32_t*)(sm + LS_BLO + bbase + 16);
                }
                #pragma unroll
                for (int mt = 0; mt < 2; mt++){
                    mma_fp16(acc[mt][nt], Ah[mt], Bh);
                    if (TP){
                        mma_fp16(acc[mt][nt], Ah[mt], Bl);
                        mma_fp16(acc[mt][nt], Al[mt], Bh);
                    }
                }
            }
        }
        // fused epilogue: mask + logit + exp, reset acc
        #pragma unroll
        for (int mt = 0; mt < 2; mt++){
            #pragma unroll
            for (int nt = 0; nt < 8; nt++){
                int cbase = colBase + n0 + nt*8 + tig*2;
                #pragma unroll
                for (int r = 0; r < 4; r++){
                    int jg = cbase + (r & 1);
                    int slot = mt*2 + (r >> 1);
                    float lp = acc[mt][nt][r] * INV_T;
                    if (TP){
                        int myrow = rt*128 + m0 + mt*16 + g + (r >> 1)*8;
                        if (jg < nposE && jg != myrow){
                            slpp[slot] += lp;
                            sexp[slot] += __expf(lp);
                        }
                    } else {
                        if (jg - PP < Ksel) sexp[slot] += __expf(lp);
                    }
                    acc[mt][nt][r] = 0.f;
                }
            }
        }
    }
    #pragma unroll
    for (int s = 0; s < 4; s++){
        if (TP){
            slpp[s] += __shfl_xor_sync(0xffffffffu, slpp[s], 1);
            slpp[s] += __shfl_xor_sync(0xffffffffu, slpp[s], 2);
        }
        sexp[s] += __shfl_xor_sync(0xffffffffu, sexp[s], 1);
        sexp[s] += __shfl_xor_sync(0xffffffffu, sexp[s], 2);
    }
    if (tig == 0){
        #pragma unroll
        for (int s = 0; s < 4; s++){
            int lrow = m0 + (s >> 1)*16 + g + (s & 1)*8;
            redL[lrow][warpn] = slpp[s];
            redE[lrow][warpn] = sexp[s];
        }
    }
    __syncthreads();
    if (tid < 128){
        g_partLpp[b][sp][rt*128 + tid] = redL[tid][0] + redL[tid][1];
        g_partExp[b][sp][rt*128 + tid] = redE[tid][0] + redE[tid][1];
    }
}

// ------------------------- per-image loss + final ---------------------------
__global__ void k_final(){
    int b = blockIdx.x, tid = threadIdx.x;
    int nposE = min(g_tot[b][0], PP);
    int npairs = nposE - 1;
    float sum = 0.f; int cnt = 0;
    if (npairs > 0){
        for (int r = tid; r < nposE; r += 256){
            float sl = 0.f, se = 0.f;
            #pragma unroll
            for (int sp = 0; sp < NSPLIT; sp++){ sl += g_partLpp[b][sp][r]; se += g_partExp[b][sp][r]; }
            sum += logf(se) - sl/(float)npairs;
            cnt++;
        }
    }
    __shared__ float ssum[256];
    __shared__ int scnt[256];
    ssum[tid] = sum; scnt[tid] = cnt;
    __syncthreads();
    for (int s = 128; s > 0; s >>= 1){
        if (tid < s){ ssum[tid] += ssum[tid+s]; scnt[tid] += scnt[tid+s]; }
        __syncthreads();
    }
    if (tid == 0){
        g_imgloss[b] = (scnt[0] > 0) ? ssum[0]/(float)scnt[0] : 0.f;
        g_has[b] = (scnt[0] > 0) ? 1 : 0;
    }
}
__global__ void k_out(float* out, int B){
    float s = 0.f; int c = 0;
    for (int b = 0; b < B; b++) if (g_has[b]){ s += g_imgloss[b]; c++; }
    out[0] = s / (float)(c > 0 ? c : 1);
}

// ------------------------- launch -------------------------------------------
extern "C" void kernel_launch(void* const* d_in, const int* in_sizes, int n_in,
                              void* d_out, int out_size){
    const float* feat = (const float*)d_in[0];
    const long long* labels = (const long long*)d_in[1];
    int B = in_sizes[1] / HW;
    if (B < 1) B = 1; if (B > MAXB) B = MAXB;

    cudaFuncSetAttribute(k_simM,     cudaFuncAttributeMaxDynamicSharedMemorySize, SIM_SMEM);
    cudaFuncSetAttribute(k_lossM<1>, cudaFuncAttributeMaxDynamicSharedMemorySize, LS_SMEM);
    cudaFuncSetAttribute(k_lossM<0>, cudaFuncAttributeMaxDynamicSharedMemorySize, LS_SMEM);

    int tot = B*HW;
    int nb = (tot + 255)/256;
    k_fg  <<<nb, 256>>>(labels, tot);
    k_hdil<<<nb, 256>>>(tot);
    k_vdil<<<nb, 256>>>(tot);
    dim3 gc(NBLK, B);
    k_count  <<<gc, 256>>>();
    k_scan   <<<B, 32>>>();
    k_scatter<<<gc, 256>>>();
    int warps = B*(PP + KCc);
    k_gather<<<(warps*32 + 255)/256, 256>>>(feat, B);
    k_simM  <<<dim3(KCc/128, B), 256, SIM_SMEM>>>();
    k_select<<<B, 256>>>();
    k_lossM<1><<<dim3(PP/128, 1, B), 256, LS_SMEM>>>(0);
    k_lossM<0><<<dim3(PP/128, NSPLIT-1, B), 256, LS_SMEM>>>(1);
    k_final <<<B, 256>>>();
    k_out   <<<1, 1>>>((float*)d_out, B);
}